// round 5
// baseline (speedup 1.0000x reference)
#include <cuda_runtime.h>
#include <cuda_bf16.h>
#include <cstdint>

#define B_ 4
#define T_ 2048
#define V_ 8192
#define D_ 256
#define M_ (B_*T_)

// ---------------- scratch ----------------
__device__ float g_q[M_*D_];
__device__ float g_k[M_*D_];
__device__ float g_v[M_*D_];
__device__ float g_r[M_*D_];

// int8 two-limb operands + per-row scales
__device__ int8_t g_x1[(size_t)M_*V_];
__device__ int8_t g_x0[(size_t)M_*V_];
__device__ float  g_xs[M_];
__device__ int8_t g_w1[3*(size_t)D_*V_];
__device__ int8_t g_w0[3*(size_t)D_*V_];
__device__ float  g_ws[3*D_];
__device__ int8_t g_wo1[(size_t)V_*D_];
__device__ int8_t g_wo0[(size_t)V_*D_];
__device__ float  g_wos[V_];
__device__ int8_t g_r1[(size_t)M_*D_];
__device__ int8_t g_r0[(size_t)M_*D_];
__device__ float  g_rs[M_];

// bf16 hi/lo q,k,v for HMMA attention
__device__ __nv_bfloat16 g_qbh[(size_t)M_*D_];
__device__ __nv_bfloat16 g_qbl[(size_t)M_*D_];
__device__ __nv_bfloat16 g_kbh[(size_t)M_*D_];
__device__ __nv_bfloat16 g_kbl[(size_t)M_*D_];
__device__ __nv_bfloat16 g_vbh[(size_t)M_*D_];
__device__ __nv_bfloat16 g_vbl[(size_t)M_*D_];

// ---------------- helpers ----------------
__device__ __forceinline__ uint32_t smem_u32(const void* p){
    uint32_t a;
    asm("{ .reg .u64 t; cvta.to.shared.u64 t, %1; cvt.u32.u64 %0, t; }" : "=r"(a) : "l"(p));
    return a;
}
#define CP16(smem, gptr) \
    asm volatile("cp.async.cg.shared.global [%0], [%1], 16;" :: "r"(smem), "l"(gptr))
#define CP_COMMIT() asm volatile("cp.async.commit_group;" ::: "memory")
#define CP_WAIT1()  asm volatile("cp.async.wait_group 1;" ::: "memory")
#define CP_WAIT0()  asm volatile("cp.async.wait_group 0;" ::: "memory")

__device__ __forceinline__ void ldsm_x4(uint32_t (&r)[4], uint32_t addr){
    asm volatile("ldmatrix.sync.aligned.m8n8.x4.shared.b16 {%0,%1,%2,%3}, [%4];"
        : "=r"(r[0]), "=r"(r[1]), "=r"(r[2]), "=r"(r[3]) : "r"(addr));
}
__device__ __forceinline__ void ldsm_x4_t(uint32_t (&r)[4], uint32_t addr){
    asm volatile("ldmatrix.sync.aligned.m8n8.x4.trans.shared.b16 {%0,%1,%2,%3}, [%4];"
        : "=r"(r[0]), "=r"(r[1]), "=r"(r[2]), "=r"(r[3]) : "r"(addr));
}
__device__ __forceinline__ void mma16816(float (&d)[4], const uint32_t (&a)[4],
                                         uint32_t b0, uint32_t b1){
    asm volatile("mma.sync.aligned.m16n8k16.row.col.f32.bf16.bf16.f32 "
        "{%0,%1,%2,%3}, {%4,%5,%6,%7}, {%8,%9}, {%0,%1,%2,%3};"
        : "+f"(d[0]), "+f"(d[1]), "+f"(d[2]), "+f"(d[3])
        : "r"(a[0]), "r"(a[1]), "r"(a[2]), "r"(a[3]), "r"(b0), "r"(b1));
}
__device__ __forceinline__ void mma16832i(int (&d)[4], const uint32_t (&a)[4],
                                          uint32_t b0, uint32_t b1){
    asm volatile("mma.sync.aligned.m16n8k32.row.col.s32.s8.s8.s32 "
        "{%0,%1,%2,%3}, {%4,%5,%6,%7}, {%8,%9}, {%0,%1,%2,%3};"
        : "+r"(d[0]), "+r"(d[1]), "+r"(d[2]), "+r"(d[3])
        : "r"(a[0]), "r"(a[1]), "r"(a[2]), "r"(a[3]), "r"(b0), "r"(b1));
}

// ================= quantization: fp32 row -> int8 two-limb + scale =================
// variant A: cols = 8192, one row per 256-thread block
__global__ void __launch_bounds__(256)
quant8192_kernel(const float* __restrict__ in, int sel)
{
    int8_t *q1, *q0; float* sc; const float* src = in;
    switch (sel) {
        case 0: q1 = g_x1; q0 = g_x0; sc = g_xs; break;
        case 1: q1 = g_w1; q0 = g_w0; sc = g_ws; break;
        case 2: q1 = g_w1 + (size_t)D_*V_;   q0 = g_w0 + (size_t)D_*V_;   sc = g_ws + D_;   break;
        default: q1 = g_w1 + 2*(size_t)D_*V_; q0 = g_w0 + 2*(size_t)D_*V_; sc = g_ws + 2*D_; break;
    }
    const int row = blockIdx.x, tid = threadIdx.x;
    const float* rp = src + (size_t)row * 8192;

    float4 v[8];
    #pragma unroll
    for (int j = 0; j < 8; ++j) v[j] = *(const float4*)(rp + tid*4 + j*1024);

    float m = 0.f;
    #pragma unroll
    for (int j = 0; j < 8; ++j) {
        m = fmaxf(m, fmaxf(fmaxf(fabsf(v[j].x), fabsf(v[j].y)),
                           fmaxf(fabsf(v[j].z), fabsf(v[j].w))));
    }
    #pragma unroll
    for (int off = 16; off; off >>= 1) m = fmaxf(m, __shfl_xor_sync(~0u, m, off));
    __shared__ float red[8];
    if ((tid & 31) == 0) red[tid >> 5] = m;
    __syncthreads();
    float rm = red[0];
    #pragma unroll
    for (int w = 1; w < 8; ++w) rm = fmaxf(rm, red[w]);
    rm = fmaxf(rm, 1e-20f);
    const float si = 16256.f / rm;
    if (tid == 0) sc[row] = rm * (1.f / 16256.f);

    #pragma unroll
    for (int j = 0; j < 8; ++j) {
        float f[4] = {v[j].x, v[j].y, v[j].z, v[j].w};
        uint32_t p1 = 0, p0 = 0;
        #pragma unroll
        for (int e = 0; e < 4; ++e) {
            float fq = rintf(f[e] * si);
            float f1 = rintf(fq * 0.0078125f);
            int i1 = (int)f1;
            int i0 = (int)(fq - f1 * 128.f);
            p1 |= (uint32_t)(i1 & 255) << (e*8);
            p0 |= (uint32_t)(i0 & 255) << (e*8);
        }
        size_t idx = (size_t)row * 8192 + tid*4 + j*1024;
        *(uint32_t*)(q1 + idx) = p1;
        *(uint32_t*)(q0 + idx) = p0;
    }
}

// variant B: cols = 256, one warp per row (block = 8 rows)
__global__ void __launch_bounds__(256)
quant256_kernel(const float* __restrict__ in, int sel)
{
    int8_t *q1, *q0; float* sc; const float* src = in;
    switch (sel) {
        case 0: q1 = g_wo1; q0 = g_wo0; sc = g_wos; break;
        default: q1 = g_r1; q0 = g_r0; sc = g_rs; src = g_r; break;
    }
    const int tid = threadIdx.x, lane = tid & 31;
    const int row = blockIdx.x * 8 + (tid >> 5);
    const float* rp = src + (size_t)row * 256 + lane * 8;
    float4 a = *(const float4*)rp, b = *(const float4*)(rp + 4);

    float m = fmaxf(fmaxf(fmaxf(fabsf(a.x), fabsf(a.y)), fmaxf(fabsf(a.z), fabsf(a.w))),
                    fmaxf(fmaxf(fabsf(b.x), fabsf(b.y)), fmaxf(fabsf(b.z), fabsf(b.w))));
    #pragma unroll
    for (int off = 16; off; off >>= 1) m = fmaxf(m, __shfl_xor_sync(~0u, m, off));
    m = fmaxf(m, 1e-20f);
    const float si = 16256.f / m;
    if (lane == 0) sc[row] = m * (1.f / 16256.f);

    float f[8] = {a.x, a.y, a.z, a.w, b.x, b.y, b.z, b.w};
    uint32_t p1[2] = {0,0}, p0[2] = {0,0};
    #pragma unroll
    for (int e = 0; e < 8; ++e) {
        float fq = rintf(f[e] * si);
        float f1 = rintf(fq * 0.0078125f);
        int i1 = (int)f1;
        int i0 = (int)(fq - f1 * 128.f);
        p1[e>>2] |= (uint32_t)(i1 & 255) << ((e&3)*8);
        p0[e>>2] |= (uint32_t)(i0 & 255) << ((e&3)*8);
    }
    size_t idx = (size_t)row * 256 + lane * 8;
    *(uint2*)(q1 + idx) = make_uint2(p1[0], p1[1]);
    *(uint2*)(q0 + idx) = make_uint2(p0[0], p0[1]);
}

// ================= int8 two-limb NT GEMM =================
// C[M,N] = sA[r]*sB[c]*(S11*16384 + (S10+S01)*128) * extra
// CTA tile 128x128, BK=64 bytes, 256 threads, warp tile 64x32.
#define ISTG 40960
#define I_A1 0
#define I_A0 10240
#define I_B1 20480
#define I_B0 30720
#define ILDS 80

__device__ __forceinline__ void i8_gemm_body(
    const int8_t* __restrict__ A1, const int8_t* __restrict__ A0,
    const int8_t* __restrict__ B1, const int8_t* __restrict__ B0,
    const float* __restrict__ sA, const float* __restrict__ sB,
    float* __restrict__ C, int K, int ldC, const float* __restrict__ ep,
    int row0, int col0)
{
    extern __shared__ __align__(128) char sm[];
    const int tid  = threadIdx.x;
    const int lane = tid & 31;
    const int wid  = tid >> 5;
    const int wm   = wid >> 2;
    const int wn   = wid & 3;
    const uint32_t sbase = smem_u32(sm);

    int acch[4][4][4], accl[4][4][4];
    #pragma unroll
    for (int a = 0; a < 4; ++a)
        #pragma unroll
        for (int b = 0; b < 4; ++b)
            #pragma unroll
            for (int c = 0; c < 4; ++c) { acch[a][b][c] = 0; accl[a][b][c] = 0; }

    auto load_stage = [&](int c, int s){
        const size_t k0 = (size_t)c * 64 + (tid & 3) * 16;
        const uint32_t sb = sbase + s * ISTG;
        #pragma unroll
        for (int h = 0; h < 2; ++h) {
            const int r = (tid >> 2) + h * 64;
            const uint32_t soff = r * ILDS + (tid & 3) * 16;
            CP16(sb + I_A1 + soff, A1 + (size_t)(row0 + r) * K + k0);
            CP16(sb + I_A0 + soff, A0 + (size_t)(row0 + r) * K + k0);
            CP16(sb + I_B1 + soff, B1 + (size_t)(col0 + r) * K + k0);
            CP16(sb + I_B0 + soff, B0 + (size_t)(col0 + r) * K + k0);
        }
    };

    const uint32_t offA = (lane & 15) * ILDS + (lane >> 4) * 16;
    const uint32_t offB = ((lane & 7) + ((lane >> 4) & 1) * 8) * ILDS
                        + ((lane >> 3) & 1) * 16;

    const int NC = K / 64;

    load_stage(0, 0);
    CP_COMMIT();

    for (int c = 0; c < NC; ++c) {
        if (c + 1 < NC) { load_stage(c + 1, (c + 1) & 1); CP_COMMIT(); CP_WAIT1(); }
        else            { CP_WAIT0(); }
        __syncthreads();

        const uint32_t sb = sbase + (c & 1) * ISTG;
        #pragma unroll
        for (int kk = 0; kk < 2; ++kk) {
            const uint32_t kb = kk * 32;
            uint32_t a1[4][4], a0[4][4], b1[2][4], b0[2][4];
            #pragma unroll
            for (int mf = 0; mf < 4; ++mf)
                ldsm_x4(a1[mf], sb + I_A1 + (wm*64 + mf*16) * ILDS + kb + offA);
            #pragma unroll
            for (int g = 0; g < 2; ++g)
                ldsm_x4(b1[g], sb + I_B1 + (wn*32 + g*16) * ILDS + kb + offB);
            #pragma unroll
            for (int mf = 0; mf < 4; ++mf)
                #pragma unroll
                for (int nf = 0; nf < 4; ++nf)
                    mma16832i(acch[mf][nf], a1[mf], b1[nf>>1][(nf&1)*2], b1[nf>>1][(nf&1)*2+1]);
            #pragma unroll
            for (int g = 0; g < 2; ++g)
                ldsm_x4(b0[g], sb + I_B0 + (wn*32 + g*16) * ILDS + kb + offB);
            #pragma unroll
            for (int mf = 0; mf < 4; ++mf)
                #pragma unroll
                for (int nf = 0; nf < 4; ++nf)
                    mma16832i(accl[mf][nf], a1[mf], b0[nf>>1][(nf&1)*2], b0[nf>>1][(nf&1)*2+1]);
            #pragma unroll
            for (int mf = 0; mf < 4; ++mf)
                ldsm_x4(a0[mf], sb + I_A0 + (wm*64 + mf*16) * ILDS + kb + offA);
            #pragma unroll
            for (int mf = 0; mf < 4; ++mf)
                #pragma unroll
                for (int nf = 0; nf < 4; ++nf)
                    mma16832i(accl[mf][nf], a0[mf], b1[nf>>1][(nf&1)*2], b1[nf>>1][(nf&1)*2+1]);
        }
        __syncthreads();
    }

    const float ex = ep ? ep[0] : 1.f;
    #pragma unroll
    for (int mf = 0; mf < 4; ++mf) {
        const int r0 = row0 + wm*64 + mf*16 + (lane >> 2);
        const float qr0 = sA[r0] * ex, qr1 = sA[r0 + 8] * ex;
        #pragma unroll
        for (int nf = 0; nf < 4; ++nf) {
            const int cc = col0 + wn*32 + nf*8 + (lane & 3) * 2;
            const float qc0 = sB[cc], qc1 = sB[cc + 1];
            float2 v0, v1;
            v0.x = ((float)acch[mf][nf][0]*16384.f + (float)accl[mf][nf][0]*128.f) * qr0 * qc0;
            v0.y = ((float)acch[mf][nf][1]*16384.f + (float)accl[mf][nf][1]*128.f) * qr0 * qc1;
            v1.x = ((float)acch[mf][nf][2]*16384.f + (float)accl[mf][nf][2]*128.f) * qr1 * qc0;
            v1.y = ((float)acch[mf][nf][3]*16384.f + (float)accl[mf][nf][3]*128.f) * qr1 * qc1;
            *(float2*)(C + (size_t)r0 * ldC + cc)       = v0;
            *(float2*)(C + (size_t)(r0 + 8) * ldC + cc) = v1;
        }
    }
}

__global__ void __launch_bounds__(256, 1)
i8_qkv_kernel()
{
    const int w = blockIdx.z;
    float* Cc = (w == 0) ? g_q : (w == 1) ? g_k : g_v;
    i8_gemm_body(g_x1, g_x0,
                 g_w1 + (size_t)w * D_ * V_, g_w0 + (size_t)w * D_ * V_,
                 g_xs, g_ws + w * D_,
                 Cc, V_, D_, nullptr,
                 blockIdx.y * 128, blockIdx.x * 128);
}

__global__ void __launch_bounds__(256, 1)
i8_out_kernel(const float* __restrict__ out_scale, float* __restrict__ out)
{
    i8_gemm_body(g_r1, g_r0, g_wo1, g_wo0, g_rs, g_wos,
                 out, D_, V_, out_scale,
                 blockIdx.y * 128, blockIdx.x * 128);
}

// ================= fp32 -> bf16 hi/lo for attention operands =================
__global__ void __launch_bounds__(256)
cvt_kernel(int sel)
{
    __nv_bfloat16 *hi, *lo; const float* src;
    switch (sel) {
        case 6: hi = g_qbh; lo = g_qbl; src = g_q; break;
        case 7: hi = g_kbh; lo = g_kbl; src = g_k; break;
        default: hi = g_vbh; lo = g_vbl; src = g_v; break;
    }
    const int base = blockIdx.x * 4096 + threadIdx.x * 4;
    float4 v[4];
    #pragma unroll
    for (int j = 0; j < 4; ++j) v[j] = *(const float4*)(src + base + j * 1024);
    #pragma unroll
    for (int j = 0; j < 4; ++j) {
        const int i = base + j * 1024;
        float f[4] = {v[j].x, v[j].y, v[j].z, v[j].w};
        union { __nv_bfloat16 b[4]; uint2 u; } H, L;
        #pragma unroll
        for (int e = 0; e < 4; ++e) {
            __nv_bfloat16 h = __float2bfloat16(f[e]);
            float r = f[e] - __bfloat162float(h);
            H.b[e] = h;
            L.b[e] = __float2bfloat16(r);
        }
        *(uint2*)(hi + i) = H.u;
        *(uint2*)(lo + i) = L.u;
    }
}

// ================= HMMA attention (unchanged from R4) =================
#define AT_STRIDE 528
#define SW_STRIDE 144
#define SM_QH 0
#define SM_QL 33792
#define SM_KH 67584
#define SM_KL 101376
#define SM_VH 135168
#define SM_VL 168960
#define SM_SWH 202752
#define SM_SWL 211968
#define ATT_SMEM 221184

__global__ void __launch_bounds__(256, 1)
attn_hmma_kernel(const float* __restrict__ dlp)
{
    extern __shared__ __align__(128) char shm[];
    const int tid = threadIdx.x, lane = tid & 31, wid = tid >> 5;
    const int wm = wid >> 1, wn = wid & 1;
    const int ib = blockIdx.x, b = blockIdx.y;
    const uint32_t sb = smem_u32(shm);

    const float logit = dlp[0];
    const float decay = 1.f / (1.f + expf(-logit));
    const float l2d   = log2f(decay);

    const int qrow0 = b * T_ + ib * 64;

    #pragma unroll
    for (int it = 0; it < 8; ++it) {
        int idx = it * 256 + tid;
        int r = idx >> 5, s = idx & 31;
        uint32_t soff = r * AT_STRIDE + s * 16;
        size_t gb = ((size_t)(qrow0 + r) * D_) * 2 + s * 16;
        CP16(sb + SM_QH + soff, (const char*)g_qbh + gb);
        CP16(sb + SM_QL + soff, (const char*)g_qbl + gb);
    }
    CP_COMMIT();

    float oacc[8][2][4];
    #pragma unroll
    for (int a = 0; a < 8; ++a)
        #pragma unroll
        for (int g = 0; g < 2; ++g)
            #pragma unroll
            for (int e = 0; e < 4; ++e) oacc[a][g][e] = 0.f;

    const uint32_t offA  = (lane & 15) * AT_STRIDE + (lane >> 4) * 16;
    const uint32_t offB  = ((lane & 7) + ((lane >> 4) & 1) * 8) * AT_STRIDE
                         + ((lane >> 3) & 1) * 16;
    const uint32_t offAs = (lane & 15) * SW_STRIDE + (lane >> 4) * 16;
    const uint32_t offV  = ((lane & 7) + ((lane >> 3) & 1) * 8) * AT_STRIDE
                         + (lane >> 4) * 16;

    const int rl0 = wm * 16 + (lane >> 2);
    const float er0 = exp2f(-l2d * (float)rl0);
    const float er1 = er0 * exp2f(-l2d * 8.f);

    CP_WAIT0();
    __syncthreads();

    for (int jb = ib; jb < T_/64; ++jb) {
        int emin = (jb - ib) * 64 - 64;
        if (emin > 0 && l2d * (float)emin < -50.f) break;
        const int krow0 = b * T_ + jb * 64;

        #pragma unroll
        for (int it = 0; it < 8; ++it) {
            int idx = it * 256 + tid;
            int r = idx >> 5, s = idx & 31;
            uint32_t soff = r * AT_STRIDE + s * 16;
            size_t gb = ((size_t)(krow0 + r) * D_) * 2 + s * 16;
            CP16(sb + SM_KH + soff, (const char*)g_kbh + gb);
            CP16(sb + SM_KL + soff, (const char*)g_kbl + gb);
        }
        CP_COMMIT();
        #pragma unroll
        for (int it = 0; it < 8; ++it) {
            int idx = it * 256 + tid;
            int r = idx >> 5, s = idx & 31;
            uint32_t soff = r * AT_STRIDE + s * 16;
            size_t gb = ((size_t)(krow0 + r) * D_) * 2 + s * 16;
            CP16(sb + SM_VH + soff, (const char*)g_vbh + gb);
            CP16(sb + SM_VL + soff, (const char*)g_vbl + gb);
        }
        CP_COMMIT();
        CP_WAIT1();
        __syncthreads();

        float sacc[4][4];
        #pragma unroll
        for (int nf = 0; nf < 4; ++nf)
            #pragma unroll
            for (int e = 0; e < 4; ++e) sacc[nf][e] = 0.f;

        #pragma unroll 4
        for (int kf = 0; kf < 16; ++kf) {
            const uint32_t kb = kf * 32;
            uint32_t qh[4], ql[4], kh[2][4], kl[2][4];
            ldsm_x4(qh, sb + SM_QH + (wm*16) * AT_STRIDE + kb + offA);
            ldsm_x4(ql, sb + SM_QL + (wm*16) * AT_STRIDE + kb + offA);
            ldsm_x4(kh[0], sb + SM_KH + (wn*32)      * AT_STRIDE + kb + offB);
            ldsm_x4(kh[1], sb + SM_KH + (wn*32 + 16) * AT_STRIDE + kb + offB);
            ldsm_x4(kl[0], sb + SM_KL + (wn*32)      * AT_STRIDE + kb + offB);
            ldsm_x4(kl[1], sb + SM_KL + (wn*32 + 16) * AT_STRIDE + kb + offB);
            #pragma unroll
            for (int nf = 0; nf < 4; ++nf) {
                mma16816(sacc[nf], qh, kh[nf>>1][(nf&1)*2], kh[nf>>1][(nf&1)*2+1]);
                mma16816(sacc[nf], qh, kl[nf>>1][(nf&1)*2], kl[nf>>1][(nf&1)*2+1]);
                mma16816(sacc[nf], ql, kh[nf>>1][(nf&1)*2], kh[nf>>1][(nf&1)*2+1]);
            }
        }

        const float wbase = exp2f(l2d * (float)((jb - ib) * 64 - 1));
        const bool diag = (jb == ib);
        #pragma unroll
        for (int nf = 0; nf < 4; ++nf) {
            const int cl = wn*32 + nf*8 + (lane & 3)*2;
            float ec0 = exp2f(l2d * (float)cl);
            float ec1 = ec0 * decay;
            float w00 = wbase*ec0*er0, w01 = wbase*ec1*er0;
            float w10 = wbase*ec0*er1, w11 = wbase*ec1*er1;
            if (diag) {
                if (cl     <= rl0)     w00 = 0.f;
                if (cl + 1 <= rl0)     w01 = 0.f;
                if (cl     <= rl0 + 8) w10 = 0.f;
                if (cl + 1 <= rl0 + 8) w11 = 0.f;
            }
            float v00 = sacc[nf][0]*w00, v01 = sacc[nf][1]*w01;
            float v10 = sacc[nf][2]*w10, v11 = sacc[nf][3]*w11;

            #pragma unroll
            for (int h = 0; h < 2; ++h) {
                float a = h ? v10 : v00, c = h ? v11 : v01;
                __nv_bfloat16 ha = __float2bfloat16(a), hc = __float2bfloat16(c);
                float ra = a - __bfloat162float(ha), rc = c - __bfloat162float(hc);
                __nv_bfloat16 la = __float2bfloat16(ra), lc = __float2bfloat16(rc);
                uint32_t ph = (uint32_t)*(uint16_t*)&ha | ((uint32_t)*(uint16_t*)&hc << 16);
                uint32_t pl = (uint32_t)*(uint16_t*)&la | ((uint32_t)*(uint16_t*)&lc << 16);
                uint32_t off = (rl0 + h*8) * SW_STRIDE + cl * 2;
                *(uint32_t*)(shm + SM_SWH + off) = ph;
                *(uint32_t*)(shm + SM_SWL + off) = pl;
            }
        }

        CP_WAIT0();
        __syncthreads();

        uint32_t sh4[4][4], sl4[4][4];
        #pragma unroll
        for (int kf = 0; kf < 4; ++kf) {
            ldsm_x4(sh4[kf], sb + SM_SWH + (wm*16) * SW_STRIDE + kf*32 + offAs);
            ldsm_x4(sl4[kf], sb + SM_SWL + (wm*16) * SW_STRIDE + kf*32 + offAs);
        }
        #pragma unroll
        for (int nb = 0; nb < 8; ++nb) {
            const uint32_t d0b = (uint32_t)(wn*128 + nb*16) * 2;
            #pragma unroll
            for (int kf = 0; kf < 4; ++kf) {
                uint32_t vh[4], vl[4];
                const uint32_t va = sb + (kf*16) * AT_STRIDE + d0b + offV;
                ldsm_x4_t(vh, va + SM_VH);
                ldsm_x4_t(vl, va + SM_VL);
                mma16816(oacc[nb][0], sh4[kf], vh[0], vh[1]);
                mma16816(oacc[nb][1], sh4[kf], vh[2], vh[3]);
                mma16816(oacc[nb][0], sh4[kf], vl[0], vl[1]);
                mma16816(oacc[nb][1], sh4[kf], vl[2], vl[3]);
                mma16816(oacc[nb][0], sl4[kf], vh[0], vh[1]);
                mma16816(oacc[nb][1], sl4[kf], vh[2], vh[3]);
            }
        }
        __syncthreads();
    }

    float* rb = g_r + (size_t)(qrow0 + wm*16 + (lane >> 2)) * D_;
    #pragma unroll
    for (int nb = 0; nb < 8; ++nb) {
        #pragma unroll
        for (int g = 0; g < 2; ++g) {
            const int c = wn*128 + nb*16 + g*8 + (lane & 3) * 2;
            float2 v0 = { oacc[nb][g][0], oacc[nb][g][1] };
            float2 v1 = { oacc[nb][g][2], oacc[nb][g][3] };
            *(float2*)(rb + c)           = v0;
            *(float2*)(rb + 8 * D_ + c)  = v1;
        }
    }
}

// ================= launch =================
#define IDSM_BYTES (2*ISTG)

extern "C" void kernel_launch(void* const* d_in, const int* in_sizes, int n_in,
                              void* d_out, int out_size)
{
    const float* x  = (const float*)d_in[0];
    const float* wq = (const float*)d_in[1];
    const float* wk = (const float*)d_in[2];
    const float* wv = (const float*)d_in[3];
    const float* wo = (const float*)d_in[4];
    const float* dl = (const float*)d_in[5];
    const float* os = (const float*)d_in[6];
    float* out = (float*)d_out;

    cudaFuncSetAttribute(i8_qkv_kernel, cudaFuncAttributeMaxDynamicSharedMemorySize, IDSM_BYTES);
    cudaFuncSetAttribute(i8_out_kernel, cudaFuncAttributeMaxDynamicSharedMemorySize, IDSM_BYTES);
    cudaFuncSetAttribute(attn_hmma_kernel, cudaFuncAttributeMaxDynamicSharedMemorySize, ATT_SMEM);

    quant8192_kernel<<<M_, 256>>>(x,  0);
    quant8192_kernel<<<D_, 256>>>(wq, 1);
    quant8192_kernel<<<D_, 256>>>(wk, 2);
    quant8192_kernel<<<D_, 256>>>(wv, 3);
    quant256_kernel<<<V_/8, 256>>>(wo, 0);

    i8_qkv_kernel<<<dim3(2, 64, 3), 256, IDSM_BYTES>>>();

    cvt_kernel<<<(M_*D_)/4096, 256>>>(6);
    cvt_kernel<<<(M_*D_)/4096, 256>>>(7);
    cvt_kernel<<<(M_*D_)/4096, 256>>>(8);

    attn_hmma_kernel<<<dim3(T_/64, B_), 256, ATT_SMEM>>>(dl);

    quant256_kernel<<<M_/8, 256>>>(nullptr, 1);

    i8_out_kernel<<<dim3(64, 64), 256, IDSM_BYTES>>>(os, out);
}

// round 6
// speedup vs baseline: 2.5478x; 2.5478x over previous
#include <cuda_runtime.h>
#include <cuda_bf16.h>
#include <cstdint>

#define B_ 4
#define T_ 2048
#define V_ 8192
#define D_ 256
#define M_ (B_*T_)   // 8192 rows of (b,t)

// ---------------- scratch (device globals; no allocs allowed) ----------------
__device__ __nv_bfloat16 g_xh[(size_t)M_*V_];
__device__ __nv_bfloat16 g_xl[(size_t)M_*V_];
__device__ __nv_bfloat16 g_wh[3*(size_t)D_*V_];
__device__ __nv_bfloat16 g_wl[3*(size_t)D_*V_];
__device__ __nv_bfloat16 g_woh[(size_t)V_*D_];
__device__ __nv_bfloat16 g_wol[(size_t)V_*D_];
__device__ __nv_bfloat16 g_rh[(size_t)M_*D_];
__device__ __nv_bfloat16 g_rl[(size_t)M_*D_];

// bf16 hi/lo q,k,v (written directly by qkv GEMM epilogue)
__device__ __nv_bfloat16 g_qbh[(size_t)M_*D_];
__device__ __nv_bfloat16 g_qbl[(size_t)M_*D_];
__device__ __nv_bfloat16 g_kbh[(size_t)M_*D_];
__device__ __nv_bfloat16 g_kbl[(size_t)M_*D_];
__device__ __nv_bfloat16 g_vbh[(size_t)M_*D_];
__device__ __nv_bfloat16 g_vbl[(size_t)M_*D_];

// ---------------- helpers ----------------
__device__ __forceinline__ uint32_t smem_u32(const void* p){
    uint32_t a;
    asm("{ .reg .u64 t; cvta.to.shared.u64 t, %1; cvt.u32.u64 %0, t; }" : "=r"(a) : "l"(p));
    return a;
}
#define CP16(smem, gptr) \
    asm volatile("cp.async.cg.shared.global [%0], [%1], 16;" :: "r"(smem), "l"(gptr))
#define CP_COMMIT() asm volatile("cp.async.commit_group;" ::: "memory")
#define CP_WAIT1()  asm volatile("cp.async.wait_group 1;" ::: "memory")
#define CP_WAIT0()  asm volatile("cp.async.wait_group 0;" ::: "memory")

__device__ __forceinline__ void ldsm_x4(uint32_t (&r)[4], uint32_t addr){
    asm volatile("ldmatrix.sync.aligned.m8n8.x4.shared.b16 {%0,%1,%2,%3}, [%4];"
        : "=r"(r[0]), "=r"(r[1]), "=r"(r[2]), "=r"(r[3]) : "r"(addr));
}
__device__ __forceinline__ void ldsm_x4_t(uint32_t (&r)[4], uint32_t addr){
    asm volatile("ldmatrix.sync.aligned.m8n8.x4.trans.shared.b16 {%0,%1,%2,%3}, [%4];"
        : "=r"(r[0]), "=r"(r[1]), "=r"(r[2]), "=r"(r[3]) : "r"(addr));
}
__device__ __forceinline__ void mma16816(float (&d)[4], const uint32_t (&a)[4],
                                         uint32_t b0, uint32_t b1){
    asm volatile("mma.sync.aligned.m16n8k16.row.col.f32.bf16.bf16.f32 "
        "{%0,%1,%2,%3}, {%4,%5,%6,%7}, {%8,%9}, {%0,%1,%2,%3};"
        : "+f"(d[0]), "+f"(d[1]), "+f"(d[2]), "+f"(d[3])
        : "r"(a[0]), "r"(a[1]), "r"(a[2]), "r"(a[3]), "r"(b0), "r"(b1));
}
__device__ __forceinline__ uint32_t pack_hilo(float a, float c,
                                              __nv_bfloat16& ra, __nv_bfloat16& rc){
    ra = __float2bfloat16(a);
    rc = __float2bfloat16(c);
    return (uint32_t)*(uint16_t*)&ra | ((uint32_t)*(uint16_t*)&rc << 16);
}

// ================= conversion kernel: fp32 -> bf16 hi/lo (inputs only) =================
__global__ void __launch_bounds__(256)
cvt_kernel(const float* __restrict__ in, int sel)
{
    __nv_bfloat16 *hi, *lo;
    switch (sel) {
        case 0: hi = g_xh;               lo = g_xl;               break;
        case 1: hi = g_wh;               lo = g_wl;               break;
        case 2: hi = g_wh + (size_t)D_*V_;   lo = g_wl + (size_t)D_*V_;   break;
        case 3: hi = g_wh + 2*(size_t)D_*V_; lo = g_wl + 2*(size_t)D_*V_; break;
        default: hi = g_woh;             lo = g_wol;              break;
    }
    const int base = blockIdx.x * 4096 + threadIdx.x * 4;
    float4 v[4];
    #pragma unroll
    for (int j = 0; j < 4; ++j) v[j] = *(const float4*)(in + base + j * 1024);
    #pragma unroll
    for (int j = 0; j < 4; ++j) {
        const int i = base + j * 1024;
        float f[4] = {v[j].x, v[j].y, v[j].z, v[j].w};
        union { __nv_bfloat16 b[4]; uint2 u; } H, L;
        #pragma unroll
        for (int e = 0; e < 4; ++e) {
            __nv_bfloat16 h = __float2bfloat16(f[e]);
            float r = f[e] - __bfloat162float(h);
            H.b[e] = h;
            L.b[e] = __float2bfloat16(r);
        }
        *(uint2*)(hi + i) = H.u;
        *(uint2*)(lo + i) = L.u;
    }
}

// ================= HMMA split-precision NT GEMM =================
// C = (Ah+Al)(Bh+Bl)^T * scale via Ah*Bh + Ah*Bl + Al*Bh
// CTA tile 128x128, BK=32, 256 threads, warp tile 64x32.
// BOUT=0: fp32 output Cf;  BOUT=1: bf16 hi/lo output Ch/Cl.
#define STG 40960
#define T_AH 0
#define T_AL 10240
#define T_BH 20480
#define T_BL 30720
#define LDS_B 80

template<int BOUT>
__device__ __forceinline__ void hmma_gemm_body(
    const __nv_bfloat16* __restrict__ Agh, const __nv_bfloat16* __restrict__ Agl,
    const __nv_bfloat16* __restrict__ Bgh, const __nv_bfloat16* __restrict__ Bgl,
    float* __restrict__ Cf, __nv_bfloat16* __restrict__ Ch, __nv_bfloat16* __restrict__ Cl,
    int K, int ldC, float scale, int row0, int col0)
{
    extern __shared__ __align__(128) char sm[];
    const int tid  = threadIdx.x;
    const int lane = tid & 31;
    const int wid  = tid >> 5;
    const int wm   = wid >> 2;
    const int wn   = wid & 3;
    const uint32_t sbase = smem_u32(sm);

    float acc[4][4][4];
    #pragma unroll
    for (int a = 0; a < 4; ++a)
        #pragma unroll
        for (int b = 0; b < 4; ++b)
            #pragma unroll
            for (int c = 0; c < 4; ++c) acc[a][b][c] = 0.f;

    const int lrow = tid >> 2, lseg = tid & 3;

    auto load_stage = [&](int c, int s){
        const size_t k0 = (size_t)c * 32 + lseg * 8;
        const uint32_t sb = sbase + s * STG;
        #pragma unroll
        for (int h = 0; h < 2; ++h) {
            const int r = lrow + h * 64;
            const uint32_t soff = r * LDS_B + lseg * 16;
            CP16(sb + T_AH + soff, Agh + (size_t)(row0 + r) * K + k0);
            CP16(sb + T_AL + soff, Agl + (size_t)(row0 + r) * K + k0);
            CP16(sb + T_BH + soff, Bgh + (size_t)(col0 + r) * K + k0);
            CP16(sb + T_BL + soff, Bgl + (size_t)(col0 + r) * K + k0);
        }
    };

    const uint32_t offA = (lane & 15) * LDS_B + (lane >> 4) * 16;
    const uint32_t offB = ((lane & 7) + ((lane >> 4) & 1) * 8) * LDS_B
                        + ((lane >> 3) & 1) * 16;

    const int NC = K / 32;

    load_stage(0, 0);
    CP_COMMIT();

    for (int c = 0; c < NC; ++c) {
        if (c + 1 < NC) { load_stage(c + 1, (c + 1) & 1); CP_COMMIT(); CP_WAIT1(); }
        else            { CP_WAIT0(); }
        __syncthreads();

        const uint32_t sb = sbase + (c & 1) * STG;
        #pragma unroll
        for (int kk = 0; kk < 2; ++kk) {
            const uint32_t kb = kk * 32;
            uint32_t ah[4][4], al[4][4], bh[2][4], bl[2][4];
            #pragma unroll
            for (int mf = 0; mf < 4; ++mf)
                ldsm_x4(ah[mf], sb + T_AH + (wm*64 + mf*16) * LDS_B + kb + offA);
            #pragma unroll
            for (int g = 0; g < 2; ++g)
                ldsm_x4(bh[g], sb + T_BH + (wn*32 + g*16) * LDS_B + kb + offB);
            #pragma unroll
            for (int mf = 0; mf < 4; ++mf)
                #pragma unroll
                for (int nf = 0; nf < 4; ++nf)
                    mma16816(acc[mf][nf], ah[mf], bh[nf>>1][(nf&1)*2], bh[nf>>1][(nf&1)*2+1]);
            #pragma unroll
            for (int g = 0; g < 2; ++g)
                ldsm_x4(bl[g], sb + T_BL + (wn*32 + g*16) * LDS_B + kb + offB);
            #pragma unroll
            for (int mf = 0; mf < 4; ++mf)
                #pragma unroll
                for (int nf = 0; nf < 4; ++nf)
                    mma16816(acc[mf][nf], ah[mf], bl[nf>>1][(nf&1)*2], bl[nf>>1][(nf&1)*2+1]);
            #pragma unroll
            for (int mf = 0; mf < 4; ++mf)
                ldsm_x4(al[mf], sb + T_AL + (wm*64 + mf*16) * LDS_B + kb + offA);
            #pragma unroll
            for (int mf = 0; mf < 4; ++mf)
                #pragma unroll
                for (int nf = 0; nf < 4; ++nf)
                    mma16816(acc[mf][nf], al[mf], bh[nf>>1][(nf&1)*2], bh[nf>>1][(nf&1)*2+1]);
        }
        __syncthreads();
    }

    #pragma unroll
    for (int mf = 0; mf < 4; ++mf) {
        const int r0 = row0 + wm*64 + mf*16 + (lane >> 2);
        #pragma unroll
        for (int nf = 0; nf < 4; ++nf) {
            const int cc = col0 + wn*32 + nf*8 + (lane & 3) * 2;
            if (BOUT == 0) {
                float2 v0 = { acc[mf][nf][0] * scale, acc[mf][nf][1] * scale };
                float2 v1 = { acc[mf][nf][2] * scale, acc[mf][nf][3] * scale };
                *(float2*)(Cf + (size_t)r0 * ldC + cc)       = v0;
                *(float2*)(Cf + (size_t)(r0 + 8) * ldC + cc) = v1;
            } else {
                #pragma unroll
                for (int h = 0; h < 2; ++h) {
                    float a = acc[mf][nf][h*2], c = acc[mf][nf][h*2+1];
                    __nv_bfloat16 ha, hc;
                    uint32_t ph = pack_hilo(a, c, ha, hc);
                    float la = a - __bfloat162float(ha), lc = c - __bfloat162float(hc);
                    __nv_bfloat16 t0, t1;
                    uint32_t pl = pack_hilo(la, lc, t0, t1);
                    *(uint32_t*)(Ch + (size_t)(r0 + h*8) * ldC + cc) = ph;
                    *(uint32_t*)(Cl + (size_t)(r0 + h*8) * ldC + cc) = pl;
                }
            }
        }
    }
}

__global__ void __launch_bounds__(256, 2)
hmma_qkv_kernel()
{
    const int w = blockIdx.z;
    const __nv_bfloat16* Bh = g_wh + (size_t)w * D_ * V_;
    const __nv_bfloat16* Bl = g_wl + (size_t)w * D_ * V_;
    __nv_bfloat16* Ch = (w == 0) ? g_qbh : (w == 1) ? g_kbh : g_vbh;
    __nv_bfloat16* Cl = (w == 0) ? g_qbl : (w == 1) ? g_kbl : g_vbl;
    hmma_gemm_body<1>(g_xh, g_xl, Bh, Bl, nullptr, Ch, Cl, V_, D_, 1.0f,
                      blockIdx.y * 128, blockIdx.x * 128);
}

__global__ void __launch_bounds__(256, 2)
hmma_out_kernel(const float* __restrict__ out_scale, float* __restrict__ out)
{
    hmma_gemm_body<0>(g_rh, g_rl, g_woh, g_wol, out, nullptr, nullptr,
                      D_, V_, out_scale[0], blockIdx.y * 128, blockIdx.x * 128);
}

// ================= HMMA attention (R4 structure, bf16 hi/lo output fused) =================
#define AT_STRIDE 528
#define SW_STRIDE 144
#define SM_QH 0
#define SM_QL 33792
#define SM_KH 67584
#define SM_KL 101376
#define SM_VH 135168
#define SM_VL 168960
#define SM_SWH 202752
#define SM_SWL 211968
#define ATT_SMEM 221184

__global__ void __launch_bounds__(256, 1)
attn_hmma_kernel(const float* __restrict__ dlp)
{
    extern __shared__ __align__(128) char shm[];
    const int tid = threadIdx.x, lane = tid & 31, wid = tid >> 5;
    const int wm = wid >> 1, wn = wid & 1;
    const int ib = blockIdx.x, b = blockIdx.y;
    const uint32_t sb = smem_u32(shm);

    const float logit = dlp[0];
    const float decay = 1.f / (1.f + expf(-logit));
    const float l2d   = log2f(decay);

    const int qrow0 = b * T_ + ib * 64;

    #pragma unroll
    for (int it = 0; it < 8; ++it) {
        int idx = it * 256 + tid;
        int r = idx >> 5, s = idx & 31;
        uint32_t soff = r * AT_STRIDE + s * 16;
        size_t gb = ((size_t)(qrow0 + r) * D_) * 2 + s * 16;
        CP16(sb + SM_QH + soff, (const char*)g_qbh + gb);
        CP16(sb + SM_QL + soff, (const char*)g_qbl + gb);
    }
    CP_COMMIT();

    float oacc[8][2][4];
    #pragma unroll
    for (int a = 0; a < 8; ++a)
        #pragma unroll
        for (int g = 0; g < 2; ++g)
            #pragma unroll
            for (int e = 0; e < 4; ++e) oacc[a][g][e] = 0.f;

    const uint32_t offA  = (lane & 15) * AT_STRIDE + (lane >> 4) * 16;
    const uint32_t offB  = ((lane & 7) + ((lane >> 4) & 1) * 8) * AT_STRIDE
                         + ((lane >> 3) & 1) * 16;
    const uint32_t offAs = (lane & 15) * SW_STRIDE + (lane >> 4) * 16;
    const uint32_t offV  = ((lane & 7) + ((lane >> 3) & 1) * 8) * AT_STRIDE
                         + (lane >> 4) * 16;

    const int rl0 = wm * 16 + (lane >> 2);
    const float er0 = exp2f(-l2d * (float)rl0);
    const float er1 = er0 * exp2f(-l2d * 8.f);

    CP_WAIT0();
    __syncthreads();

    for (int jb = ib; jb < T_/64; ++jb) {
        int emin = (jb - ib) * 64 - 64;
        if (emin > 0 && l2d * (float)emin < -50.f) break;
        const int krow0 = b * T_ + jb * 64;

        #pragma unroll
        for (int it = 0; it < 8; ++it) {
            int idx = it * 256 + tid;
            int r = idx >> 5, s = idx & 31;
            uint32_t soff = r * AT_STRIDE + s * 16;
            size_t gb = ((size_t)(krow0 + r) * D_) * 2 + s * 16;
            CP16(sb + SM_KH + soff, (const char*)g_kbh + gb);
            CP16(sb + SM_KL + soff, (const char*)g_kbl + gb);
        }
        CP_COMMIT();
        #pragma unroll
        for (int it = 0; it < 8; ++it) {
            int idx = it * 256 + tid;
            int r = idx >> 5, s = idx & 31;
            uint32_t soff = r * AT_STRIDE + s * 16;
            size_t gb = ((size_t)(krow0 + r) * D_) * 2 + s * 16;
            CP16(sb + SM_VH + soff, (const char*)g_vbh + gb);
            CP16(sb + SM_VL + soff, (const char*)g_vbl + gb);
        }
        CP_COMMIT();
        CP_WAIT1();
        __syncthreads();

        float sacc[4][4];
        #pragma unroll
        for (int nf = 0; nf < 4; ++nf)
            #pragma unroll
            for (int e = 0; e < 4; ++e) sacc[nf][e] = 0.f;

        #pragma unroll 4
        for (int kf = 0; kf < 16; ++kf) {
            const uint32_t kb = kf * 32;
            uint32_t qh[4], ql[4], kh[2][4], kl[2][4];
            ldsm_x4(qh, sb + SM_QH + (wm*16) * AT_STRIDE + kb + offA);
            ldsm_x4(ql, sb + SM_QL + (wm*16) * AT_STRIDE + kb + offA);
            ldsm_x4(kh[0], sb + SM_KH + (wn*32)      * AT_STRIDE + kb + offB);
            ldsm_x4(kh[1], sb + SM_KH + (wn*32 + 16) * AT_STRIDE + kb + offB);
            ldsm_x4(kl[0], sb + SM_KL + (wn*32)      * AT_STRIDE + kb + offB);
            ldsm_x4(kl[1], sb + SM_KL + (wn*32 + 16) * AT_STRIDE + kb + offB);
            #pragma unroll
            for (int nf = 0; nf < 4; ++nf) {
                mma16816(sacc[nf], qh, kh[nf>>1][(nf&1)*2], kh[nf>>1][(nf&1)*2+1]);
                mma16816(sacc[nf], qh, kl[nf>>1][(nf&1)*2], kl[nf>>1][(nf&1)*2+1]);
                mma16816(sacc[nf], ql, kh[nf>>1][(nf&1)*2], kh[nf>>1][(nf&1)*2+1]);
            }
        }

        const float wbase = exp2f(l2d * (float)((jb - ib) * 64 - 1));
        const bool diag = (jb == ib);
        #pragma unroll
        for (int nf = 0; nf < 4; ++nf) {
            const int cl = wn*32 + nf*8 + (lane & 3)*2;
            float ec0 = exp2f(l2d * (float)cl);
            float ec1 = ec0 * decay;
            float w00 = wbase*ec0*er0, w01 = wbase*ec1*er0;
            float w10 = wbase*ec0*er1, w11 = wbase*ec1*er1;
            if (diag) {
                if (cl     <= rl0)     w00 = 0.f;
                if (cl + 1 <= rl0)     w01 = 0.f;
                if (cl     <= rl0 + 8) w10 = 0.f;
                if (cl + 1 <= rl0 + 8) w11 = 0.f;
            }
            float v00 = sacc[nf][0]*w00, v01 = sacc[nf][1]*w01;
            float v10 = sacc[nf][2]*w10, v11 = sacc[nf][3]*w11;

            #pragma unroll
            for (int h = 0; h < 2; ++h) {
                float a = h ? v10 : v00, c = h ? v11 : v01;
                __nv_bfloat16 ha, hc;
                uint32_t ph = pack_hilo(a, c, ha, hc);
                float ra = a - __bfloat162float(ha), rc = c - __bfloat162float(hc);
                __nv_bfloat16 t0, t1;
                uint32_t pl = pack_hilo(ra, rc, t0, t1);
                uint32_t off = (rl0 + h*8) * SW_STRIDE + cl * 2;
                *(uint32_t*)(shm + SM_SWH + off) = ph;
                *(uint32_t*)(shm + SM_SWL + off) = pl;
            }
        }

        CP_WAIT0();
        __syncthreads();

        uint32_t sh4[4][4], sl4[4][4];
        #pragma unroll
        for (int kf = 0; kf < 4; ++kf) {
            ldsm_x4(sh4[kf], sb + SM_SWH + (wm*16) * SW_STRIDE + kf*32 + offAs);
            ldsm_x4(sl4[kf], sb + SM_SWL + (wm*16) * SW_STRIDE + kf*32 + offAs);
        }
        #pragma unroll
        for (int nb = 0; nb < 8; ++nb) {
            const uint32_t d0b = (uint32_t)(wn*128 + nb*16) * 2;
            #pragma unroll
            for (int kf = 0; kf < 4; ++kf) {
                uint32_t vh[4], vl[4];
                const uint32_t va = sb + (kf*16) * AT_STRIDE + d0b + offV;
                ldsm_x4_t(vh, va + SM_VH);
                ldsm_x4_t(vl, va + SM_VL);
                mma16816(oacc[nb][0], sh4[kf], vh[0], vh[1]);
                mma16816(oacc[nb][1], sh4[kf], vh[2], vh[3]);
                mma16816(oacc[nb][0], sh4[kf], vl[0], vl[1]);
                mma16816(oacc[nb][1], sh4[kf], vl[2], vl[3]);
                mma16816(oacc[nb][0], sl4[kf], vh[0], vh[1]);
                mma16816(oacc[nb][1], sl4[kf], vh[2], vh[3]);
            }
        }
        __syncthreads();
    }

    // ---- fused epilogue: write r directly as bf16 hi/lo ----
    const size_t rrow = (size_t)(qrow0 + wm*16 + (lane >> 2)) * D_;
    #pragma unroll
    for (int nb = 0; nb < 8; ++nb) {
        #pragma unroll
        for (int g = 0; g < 2; ++g) {
            const int c = wn*128 + nb*16 + g*8 + (lane & 3) * 2;
            #pragma unroll
            for (int h = 0; h < 2; ++h) {
                float a = oacc[nb][g][h*2], cc = oacc[nb][g][h*2+1];
                __nv_bfloat16 ha, hc;
                uint32_t ph = pack_hilo(a, cc, ha, hc);
                float la = a - __bfloat162float(ha), lc = cc - __bfloat162float(hc);
                __nv_bfloat16 t0, t1;
                uint32_t pl = pack_hilo(la, lc, t0, t1);
                *(uint32_t*)(g_rh + rrow + (size_t)h * 8 * D_ + c) = ph;
                *(uint32_t*)(g_rl + rrow + (size_t)h * 8 * D_ + c) = pl;
            }
        }
    }
}

// ================= launch =================
#define DSMEM_BYTES (2*STG)

extern "C" void kernel_launch(void* const* d_in, const int* in_sizes, int n_in,
                              void* d_out, int out_size)
{
    const float* x  = (const float*)d_in[0];
    const float* wq = (const float*)d_in[1];
    const float* wk = (const float*)d_in[2];
    const float* wv = (const float*)d_in[3];
    const float* wo = (const float*)d_in[4];
    const float* dl = (const float*)d_in[5];
    const float* os = (const float*)d_in[6];
    float* out = (float*)d_out;

    cudaFuncSetAttribute(hmma_qkv_kernel, cudaFuncAttributeMaxDynamicSharedMemorySize, DSMEM_BYTES);
    cudaFuncSetAttribute(hmma_out_kernel, cudaFuncAttributeMaxDynamicSharedMemorySize, DSMEM_BYTES);
    cudaFuncSetAttribute(attn_hmma_kernel, cudaFuncAttributeMaxDynamicSharedMemorySize, ATT_SMEM);

    cvt_kernel<<<((size_t)M_*V_)/4096, 256>>>(x,  0);
    cvt_kernel<<<((size_t)D_*V_)/4096, 256>>>(wq, 1);
    cvt_kernel<<<((size_t)D_*V_)/4096, 256>>>(wk, 2);
    cvt_kernel<<<((size_t)D_*V_)/4096, 256>>>(wv, 3);
    cvt_kernel<<<((size_t)D_*V_)/4096, 256>>>(wo, 4);

    hmma_qkv_kernel<<<dim3(2, 64, 3), 256, DSMEM_BYTES>>>();

    attn_hmma_kernel<<<dim3(T_/64, B_), 256, ATT_SMEM>>>(dl);

    hmma_out_kernel<<<dim3(64, 64), 256, DSMEM_BYTES>>>(os, out);
}